// round 2
// baseline (speedup 1.0000x reference)
#include <cuda_runtime.h>
#include <math.h>

#define BSZ 8
#define NQ 900
#define DD 256
#define KK 10
#define ROWS (BSZ*NQ)        /* 7200  */
#define FMAX (ROWS*KK)       /* 72000 */
#define WDIM 512

// ---------------- scratch (static __device__ arrays; no allocation) ----------
__device__ float4 g_pm[FMAX];              // log-position mat per compact entry
__device__ float  g_w[FMAX];               // wave scale per compact entry
__device__ float  g_oval[FMAX];            // iou*mk per compact entry
__device__ float  g_mkval[FMAX];           // mk per compact entry
__device__ float  g_H[(size_t)FMAX*DD];    // relu(features@W3+b3)
__device__ float  g_feat[(size_t)FMAX*DD]; // H@W4+b4
__device__ int    g_rowbase[ROWS];
__device__ int    g_rowcnt[ROWS];
__device__ float  g_T1[(size_t)ROWS*DD];   // relu(tgt@W1+b1)
__device__ float  g_Z[(size_t)ROWS*DD];    // cur*neg + agg
__device__ float  g_agg[(size_t)ROWS*DD];
__device__ float  g_s64[DD];               // colsum of W3[0:64,:]
__device__ int    g_count;

// ---------------- init: zero counter + rank-1 colsum of W3[:64] -------------
__global__ void k_init(const float* __restrict__ W3) {
    int n = threadIdx.x;
    float s = 0.f;
    #pragma unroll 8
    for (int r = 0; r < 64; r++) s += W3[r*DD + n];
    g_s64[n] = s;
    if (n == 0) g_count = 0;
}

// ---------------- top-K + mask logic + compact entry build ------------------
__global__ void k_topk(const float* __restrict__ ious,
                       const float* __restrict__ gmask,
                       const float* __restrict__ bboxes) {
    __shared__ float ov[NQ];
    __shared__ float rv[256];
    __shared__ int   ri[256];
    __shared__ float s_kv[KK];
    __shared__ int   s_kidx[KK];

    int r = blockIdx.x;
    int b = r / NQ, i = r % NQ;
    int tid = threadIdx.x;
    const float* Mrow = gmask + b*NQ;
    float neg_i = 1.0f - Mrow[i];
    if (neg_i == 0.0f) {          // row fully masked: no active entries
        if (tid == 0) { g_rowbase[r] = 0; g_rowcnt[r] = 0; }
        return;
    }
    const float* irow = ious + (size_t)r * NQ;
    for (int j = tid; j < NQ; j += 256) ov[j] = irow[j] * Mrow[j] * neg_i;
    __syncthreads();

    // iterative top-10 (ties -> smallest index, matching stable argsort)
    for (int t = 0; t < KK; t++) {
        float bv = -3.4e38f; int bi = NQ;
        for (int j = tid; j < NQ; j += 256) {
            float v = ov[j];
            if (v > bv || (v == bv && j < bi)) { bv = v; bi = j; }
        }
        rv[tid] = bv; ri[tid] = bi;
        __syncthreads();
        for (int s = 128; s > 0; s >>= 1) {
            if (tid < s) {
                float v2 = rv[tid+s]; int i2 = ri[tid+s];
                if (v2 > rv[tid] || (v2 == rv[tid] && i2 < ri[tid])) {
                    rv[tid] = v2; ri[tid] = i2;
                }
            }
            __syncthreads();
        }
        if (tid == 0) { s_kv[t] = rv[0]; s_kidx[t] = ri[0]; ov[ri[0]] = -3.4e38f; }
        __syncthreads();
    }

    if (tid == 0) {
        float mkv[KK];
        int cnt = 0;
        #pragma unroll
        for (int t = 0; t < KK; t++) {
            float nmk = Mrow[s_kidx[t]];
            float mk  = (s_kv[t] >= 0.4f) ? nmk : 0.0f;   // mk = nmk * (iou>=thr)
            mkv[t] = mk;
            if (mk != 0.0f) cnt++;
        }
        int base = (cnt > 0) ? atomicAdd(&g_count, cnt) : 0;
        g_rowbase[r] = base; g_rowcnt[r] = cnt;

        const float* cb = bboxes + (size_t)r * 4;
        float ccx = 0.5f*(cb[0]+cb[2]), ccy = 0.5f*(cb[1]+cb[3]);
        float cw = cb[2]-cb[0], ch = cb[3]-cb[1];
        int s = 0;
        for (int t = 0; t < KK; t++) {
            if (mkv[t] == 0.0f) continue;
            const float* nb = bboxes + (size_t)(b*NQ + s_kidx[t]) * 4;
            float dcx = 0.5f*(nb[0]+nb[2]) - ccx;
            float dcy = 0.5f*(nb[1]+nb[3]) - ccy;
            float dw  = (nb[2]-nb[0]) - cw;
            float dh  = (nb[3]-nb[1]) - ch;
            float4 pm;
            pm.x = logf(fmaxf(fabsf(dcx), 1e-7f));
            pm.y = logf(fmaxf(fabsf(dcy), 1e-7f));
            pm.z = logf(fmaxf(fabsf(dw ), 1e-7f));
            pm.w = logf(fmaxf(fabsf(dh ), 1e-7f));
            g_pm[base+s]    = pm;
            // wave scale = cur_mask*mk = neg_i * nmk * mk
            g_w[base+s]     = neg_i * Mrow[s_kidx[t]] * mkv[t];
            g_oval[base+s]  = s_kv[t] * mkv[t];
            g_mkval[base+s] = mkv[t];
            s++;
        }
    }
}

// ---------------- GEMM1: H = relu(wave(pm,w) @ W3[64:] + b3 + oval*s64) -----
// BM=64, BN=256 (full width), BK=16. Wave features generated on the fly:
// j in [0,512): a=j>>8, sf=(j>>7)&1, f=j&127; comp=2a+sf;
// coef = 2*pi*10000^{-(f>>1)/64}; val = (sf?cos:sin)(coef*pm[comp]) * w
__global__ __launch_bounds__(256, 2)
void gemm1_fused(const float* __restrict__ B,      // W3+64*DD, [512,256]
                 const float* __restrict__ bias) { // b3
    __shared__ __align__(16) float As[16][72];
    __shared__ __align__(16) float Bs[16][256];
    __shared__ float4 s_pm[64];
    __shared__ float  s_w[64];
    __shared__ float  s_coef[64];

    int M = g_count;
    int m0 = blockIdx.x * 64;
    if (m0 >= M) return;
    int tid = threadIdx.x;

    if (tid < 64) {
        const float L2E4 = 13.28771237954945f;   // log2(10000)
        s_coef[tid] = 6.2831853071795864769f * exp2f(-(float)tid * (1.0f/64.0f) * L2E4);
        int row = m0 + tid;
        if (row < M) { s_pm[tid] = g_pm[row]; s_w[tid] = g_w[row]; }
        else { s_pm[tid] = make_float4(0.f,0.f,0.f,0.f); s_w[tid] = 0.f; }
    }
    __syncthreads();

    int tx = tid & 31, ty = tid >> 5;       // tx: 8-col group (256), ty: 8-row group (64)
    int ak = tid >> 4;                      // 0..15  (k within tile, A gen)
    int ar = (tid & 15) * 4;                // 0,4,..,60 (row base, A gen)
    int bk = tid >> 4;                      // 0..15  (k within tile, B load)
    int bc = (tid & 15) * 16;               // col base, 16 floats each

    float acc[8][8];
    #pragma unroll
    for (int p = 0; p < 8; p++)
        #pragma unroll
        for (int q = 0; q < 8; q++) acc[p][q] = 0.f;

    for (int k0 = 0; k0 < WDIM; k0 += 16) {
        // ---- generate A tile on the fly ----
        {
            int j = k0 + ak;
            int a = j >> 8, sf = (j >> 7) & 1, f = j & 127;
            int comp = 2*a + sf;
            float coef = s_coef[f >> 1];
            float4 vv;
            float* vp = (float*)&vv;
            #pragma unroll
            for (int u = 0; u < 4; u++) {
                int row = ar + u;
                const float* pmp = (const float*)&s_pm[row];
                float ang = coef * pmp[comp];
                float v = sf ? __cosf(ang) : __sinf(ang);
                vp[u] = v * s_w[row];
            }
            *(float4*)&As[ak][ar] = vv;
        }
        // ---- load B tile ----
        {
            const float* bp = B + (size_t)(k0 + bk)*DD + bc;
            *(float4*)&Bs[bk][bc+ 0] = *(const float4*)(bp+ 0);
            *(float4*)&Bs[bk][bc+ 4] = *(const float4*)(bp+ 4);
            *(float4*)&Bs[bk][bc+ 8] = *(const float4*)(bp+ 8);
            *(float4*)&Bs[bk][bc+12] = *(const float4*)(bp+12);
        }
        __syncthreads();
        #pragma unroll
        for (int k = 0; k < 16; k++) {
            float a[8], bb[8];
            *(float4*)&a[0]  = *(const float4*)&As[k][ty*8];
            *(float4*)&a[4]  = *(const float4*)&As[k][ty*8 + 4];
            *(float4*)&bb[0] = *(const float4*)&Bs[k][tx*8];
            *(float4*)&bb[4] = *(const float4*)&Bs[k][tx*8 + 4];
            #pragma unroll
            for (int p = 0; p < 8; p++)
                #pragma unroll
                for (int q = 0; q < 8; q++) acc[p][q] += a[p] * bb[q];
        }
        __syncthreads();
    }

    float bv[8], sv[8];
    #pragma unroll
    for (int q = 0; q < 8; q++) {
        int n = tx*8 + q;
        bv[q] = bias[n];
        sv[q] = g_s64[n];
    }
    #pragma unroll
    for (int p = 0; p < 8; p++) {
        int row = m0 + ty*8 + p;
        if (row >= M) continue;
        float ovl = g_oval[row];
        #pragma unroll
        for (int q = 0; q < 8; q++) {
            int n = tx*8 + q;
            float v = acc[p][q] + bv[q] + ovl * sv[q];   // rank-1 "overs" block
            g_H[(size_t)row*DD + n] = fmaxf(v, 0.f);     // relu
        }
    }
}

// ---------------- fp32 SIMT GEMM, N fixed at 256, BM=BN=128, BK=16 ----------
enum { MG2 = 1, MC1 = 2, MC2 = 3, MOUT = 4 };

template<int MODE>
__global__ __launch_bounds__(256, 2)
void gemm_k(const float* __restrict__ Aext,
            const float* __restrict__ B,
            const float* __restrict__ bias,
            const float* __restrict__ gmask,
            float* __restrict__ Cext,
            int Mext) {
    const float* A; float* C; int M;
    if (MODE == MG2)      { A = g_H;  C = g_feat; M = g_count; }
    else if (MODE == MC1) { A = Aext; C = g_T1;   M = Mext; }
    else if (MODE == MC2) { A = g_T1; C = g_Z;    M = Mext; }
    else                  { A = g_Z;  C = Cext;   M = Mext; }

    int m0 = blockIdx.x * 128;
    if (m0 >= M) return;
    int n0 = blockIdx.y * 128;

    __shared__ __align__(16) float As[16][132];
    __shared__ __align__(16) float Bs[16][128];

    int tid = threadIdx.x;
    int tx = tid & 15, ty = tid >> 4;
    int arow = tid >> 2;         // 0..63
    int ac4  = (tid & 3) * 4;    // 0,4,8,12
    int brow = tid >> 5;         // 0..7
    int bc   = (tid & 31) * 4;

    float acc[8][8];
    #pragma unroll
    for (int p = 0; p < 8; p++)
        #pragma unroll
        for (int q = 0; q < 8; q++) acc[p][q] = 0.f;

    for (int k0 = 0; k0 < DD; k0 += 16) {
        #pragma unroll
        for (int h = 0; h < 2; h++) {
            int row = m0 + arow + h*64;
            float4 v = make_float4(0.f,0.f,0.f,0.f);
            if (row < M) v = *(const float4*)(A + (size_t)row*DD + k0 + ac4);
            As[ac4+0][arow + h*64] = v.x;
            As[ac4+1][arow + h*64] = v.y;
            As[ac4+2][arow + h*64] = v.z;
            As[ac4+3][arow + h*64] = v.w;
        }
        #pragma unroll
        for (int h = 0; h < 2; h++) {
            int kr = k0 + brow + h*8;
            float4 v = *(const float4*)(B + (size_t)kr*DD + n0 + bc);
            *(float4*)&Bs[brow + h*8][bc] = v;
        }
        __syncthreads();
        #pragma unroll
        for (int k = 0; k < 16; k++) {
            float a[8], bb[8];
            *(float4*)&a[0]  = *(const float4*)&As[k][ty*8];
            *(float4*)&a[4]  = *(const float4*)&As[k][ty*8 + 4];
            *(float4*)&bb[0] = *(const float4*)&Bs[k][tx*8];
            *(float4*)&bb[4] = *(const float4*)&Bs[k][tx*8 + 4];
            #pragma unroll
            for (int p = 0; p < 8; p++)
                #pragma unroll
                for (int q = 0; q < 8; q++) acc[p][q] += a[p] * bb[q];
        }
        __syncthreads();
    }

    float bv[8];
    #pragma unroll
    for (int q = 0; q < 8; q++) bv[q] = bias[n0 + tx*8 + q];

    #pragma unroll
    for (int p = 0; p < 8; p++) {
        int row = m0 + ty*8 + p;
        if (row >= M) continue;
        float ng = 0.f;
        if (MODE == MC2 || MODE == MOUT) ng = 1.0f - gmask[row];
        #pragma unroll
        for (int q = 0; q < 8; q++) {
            int n = n0 + tx*8 + q;
            float v = acc[p][q] + bv[q];
            if (MODE == MG2) {
                C[(size_t)row*DD + n] = v;
            } else if (MODE == MC1) {
                C[(size_t)row*DD + n] = fmaxf(v, 0.f);
            } else if (MODE == MC2) {
                C[(size_t)row*DD + n] = v * ng + g_agg[(size_t)row*DD + n];
            } else { // MOUT
                C[(size_t)row*DD + n] = fmaxf(v, 0.f) * ng;
            }
        }
    }
}

// ---------------- masked max over K neighbors -------------------------------
__global__ void k_reduce() {
    int r = blockIdx.x, d = threadIdx.x;
    int base = g_rowbase[r], cnt = g_rowcnt[r];
    float m = (cnt < KK) ? 0.0f : -3.4e38f;  // missing (mk=0) entries contribute 0
    for (int e = 0; e < cnt; e++)
        m = fmaxf(m, g_mkval[base+e] * g_feat[(size_t)(base+e)*DD + d]);
    g_agg[(size_t)r*DD + d] = m;
}

// ---------------- launch ----------------------------------------------------
extern "C" void kernel_launch(void* const* d_in, const int* in_sizes, int n_in,
                              void* d_out, int out_size) {
    const float* tgt    = (const float*)d_in[0];
    const float* ious   = (const float*)d_in[1];
    const float* bboxes = (const float*)d_in[2];
    const float* gmask  = (const float*)d_in[3];
    const float* W1 = (const float*)d_in[4];  const float* b1 = (const float*)d_in[5];
    const float* W2 = (const float*)d_in[6];  const float* b2 = (const float*)d_in[7];
    const float* W3 = (const float*)d_in[8];  const float* b3 = (const float*)d_in[9];
    const float* W4 = (const float*)d_in[10]; const float* b4 = (const float*)d_in[11];
    const float* W5 = (const float*)d_in[12]; const float* b5 = (const float*)d_in[13];
    float* out = (float*)d_out;

    k_init<<<1, 256>>>(W3);
    k_topk<<<ROWS, 256>>>(ious, gmask, bboxes);

    gemm1_fused<<<(FMAX + 63) / 64, 256>>>(W3 + 64*DD, b3);

    dim3 gdyn((FMAX + 127) / 128, 2);
    dim3 gfix((ROWS + 127) / 128, 2);

    gemm_k<MG2><<<gdyn, 256>>>(nullptr, W4, b4, nullptr, nullptr, 0);
    k_reduce<<<ROWS, DD>>>();
    gemm_k<MC1><<<gfix, 256>>>(tgt,     W1, b1, nullptr, nullptr, ROWS);
    gemm_k<MC2><<<gfix, 256>>>(nullptr, W2, b2, gmask,  nullptr, ROWS);
    gemm_k<MOUT><<<gfix, 256>>>(nullptr, W5, b5, gmask, out,     ROWS);
}

// round 4
// speedup vs baseline: 2.2540x; 2.2540x over previous
#include <cuda_runtime.h>
#include <math.h>
#include <stdint.h>

#define BSZ 8
#define NQ 900
#define DD 256
#define KK 10
#define ROWS (BSZ*NQ)        /* 7200  */
#define FMAX (ROWS*KK)       /* 72000 */
#define WDIM 512

// ---------------- scratch (static __device__ arrays; no allocation) ----------
__device__ float4 g_pm[FMAX];
__device__ float  g_w[FMAX];
__device__ float  g_oval[FMAX];
__device__ float  g_mkval[FMAX];
__device__ float  g_H[(size_t)FMAX*DD];
__device__ float  g_feat[(size_t)FMAX*DD];
__device__ int    g_rowbase[ROWS];
__device__ int    g_rowcnt[ROWS];
__device__ float  g_T1[(size_t)ROWS*DD];
__device__ float  g_Z[(size_t)ROWS*DD];
__device__ float  g_agg[(size_t)ROWS*DD];
__device__ float  g_s64[DD];
__device__ int    g_count;
// transposed weights, [N][K] K-major rows
__device__ float  g_W3T[DD*WDIM];
__device__ float  g_W1T[DD*DD];
__device__ float  g_W2T[DD*DD];
__device__ float  g_W4T[DD*DD];
__device__ float  g_W5T[DD*DD];

__device__ __forceinline__ uint32_t f2tf(float f) {
    uint32_t r;
    asm("cvt.rna.tf32.f32 %0, %1;" : "=r"(r) : "f"(f));
    return r;
}
__device__ __forceinline__ void mma_tf32(float* c, const uint32_t* a, const uint32_t* b) {
    asm volatile(
        "mma.sync.aligned.m16n8k8.row.col.f32.tf32.tf32.f32 "
        "{%0,%1,%2,%3}, {%4,%5,%6,%7}, {%8,%9}, {%0,%1,%2,%3};"
        : "+f"(c[0]), "+f"(c[1]), "+f"(c[2]), "+f"(c[3])
        : "r"(a[0]), "r"(a[1]), "r"(a[2]), "r"(a[3]), "r"(b[0]), "r"(b[1]));
}

// ---------------- prep: transpose weights + s64 + counter -------------------
__global__ void k_prep(const float* __restrict__ W1, const float* __restrict__ W2,
                       const float* __restrict__ W3, const float* __restrict__ W4,
                       const float* __restrict__ W5) {
    int idx = blockIdx.x * 256 + threadIdx.x;
    if (idx < 131072) {                       // W3T [256][512] from W3[64+k][n]
        int n = idx >> 9, k = idx & 511;
        g_W3T[idx] = W3[(size_t)(64 + k) * DD + n];
    } else {
        int r = idx - 131072;
        int m = r >> 16, e = r & 65535;
        int n = e >> 8, k = e & 255;
        if      (m == 0) g_W1T[e] = W1[(size_t)k*DD + n];
        else if (m == 1) g_W2T[e] = W2[(size_t)k*DD + n];
        else if (m == 2) g_W4T[e] = W4[(size_t)k*DD + n];
        else             g_W5T[e] = W5[(size_t)k*DD + n];
    }
}
__global__ void k_init(const float* __restrict__ W3) {
    int n = threadIdx.x;
    float s = 0.f;
    #pragma unroll 8
    for (int r = 0; r < 64; r++) s += W3[r*DD + n];
    g_s64[n] = s;
    if (n == 0) g_count = 0;
}

// ---------------- top-K: one warp per row, register-resident ----------------
#define NU 29   /* ceil(900/32) */
__global__ __launch_bounds__(256)
void k_topk(const float* __restrict__ ious,
            const float* __restrict__ gmask,
            const float* __restrict__ bboxes) {
    int wid = threadIdx.x >> 5, lid = threadIdx.x & 31;
    int r = blockIdx.x * 8 + wid;
    if (r >= ROWS) return;
    int b = r / NQ, i = r % NQ;
    const float* Mrow = gmask + b*NQ;
    float neg_i = 1.0f - Mrow[i];
    if (neg_i == 0.0f) {
        if (lid == 0) { g_rowbase[r] = 0; g_rowcnt[r] = 0; }
        return;
    }
    const float* irow = ious + (size_t)r * NQ;
    float ov[NU];
    #pragma unroll
    for (int u = 0; u < NU; u++) {
        int j = lid + u*32;
        ov[u] = (j < NQ) ? irow[j] * Mrow[j] * neg_i : -3.4e38f;
    }
    float kv[KK]; int ki[KK];
    float lastv = 3.5e38f; int lasti = -1;   // round-0: nothing excluded
    #pragma unroll
    for (int t = 0; t < KK; t++) {
        float lv = -3.4e38f; int li = NQ;
        #pragma unroll
        for (int u = 0; u < NU; u++) {
            int j = lid + u*32;
            float v = ov[u];
            // exclude already-selected: (v,j) outranks or equals last winner
            bool inc = (v < lastv) || (v == lastv && j > lasti);
            if (inc && (v > lv || (v == lv && j < li))) { lv = v; li = j; }
        }
        #pragma unroll
        for (int off = 16; off > 0; off >>= 1) {
            float vv = __shfl_xor_sync(0xffffffffu, lv, off);
            int   ii = __shfl_xor_sync(0xffffffffu, li, off);
            if (vv > lv || (vv == lv && ii < li)) { lv = vv; li = ii; }
        }
        kv[t] = lv; ki[t] = li;
        lastv = lv; lasti = li;
    }
    if (lid == 0) {
        float mkv[KK];
        int cnt = 0;
        #pragma unroll
        for (int t = 0; t < KK; t++) {
            float nmk = Mrow[ki[t]];
            float mk  = (kv[t] >= 0.4f) ? nmk : 0.0f;
            mkv[t] = mk;
            if (mk != 0.0f) cnt++;
        }
        int base = (cnt > 0) ? atomicAdd(&g_count, cnt) : 0;
        g_rowbase[r] = base; g_rowcnt[r] = cnt;

        const float* cb = bboxes + (size_t)r * 4;
        float ccx = 0.5f*(cb[0]+cb[2]), ccy = 0.5f*(cb[1]+cb[3]);
        float cw = cb[2]-cb[0], ch = cb[3]-cb[1];
        int s = 0;
        #pragma unroll
        for (int t = 0; t < KK; t++) {
            if (mkv[t] == 0.0f) continue;
            const float* nb = bboxes + (size_t)(b*NQ + ki[t]) * 4;
            float dcx = 0.5f*(nb[0]+nb[2]) - ccx;
            float dcy = 0.5f*(nb[1]+nb[3]) - ccy;
            float dw  = (nb[2]-nb[0]) - cw;
            float dh  = (nb[3]-nb[1]) - ch;
            float4 pm;
            pm.x = logf(fmaxf(fabsf(dcx), 1e-7f));
            pm.y = logf(fmaxf(fabsf(dcy), 1e-7f));
            pm.z = logf(fmaxf(fabsf(dw ), 1e-7f));
            pm.w = logf(fmaxf(fabsf(dh ), 1e-7f));
            g_pm[base+s]    = pm;
            g_w[base+s]     = neg_i * Mrow[ki[t]] * mkv[t];
            g_oval[base+s]  = kv[t] * mkv[t];
            g_mkval[base+s] = mkv[t];
            s++;
        }
    }
}

// ---------------- tf32 mma.sync GEMM: 128x128 tile, BK=16 -------------------
enum { MG1 = 0, MG2 = 1, MC1 = 2, MC2 = 3, MOUT = 4 };
#define BM 128
#define BN 128
#define BK 16
#define AST 20   /* padded row stride (floats) */

template<int MODE>
__global__ __launch_bounds__(256)
void gemm_mma(const float* __restrict__ Aex,
              const float* __restrict__ bias,
              const float* __restrict__ gmask,
              float* __restrict__ Cex,
              int Mext) {
    __shared__ __align__(16) float As[BM*AST];
    __shared__ __align__(16) float Bs[BN*AST];
    __shared__ float bias_s[BN];
    __shared__ float s64_s[BN];
    __shared__ float4 pm_s[BM];
    __shared__ float w_s[BM];
    __shared__ float coef_s[64];

    const int Kd = (MODE == MG1) ? WDIM : DD;
    int M = (MODE == MG1 || MODE == MG2) ? g_count : Mext;
    int m0 = blockIdx.x * BM;
    if (m0 >= M) return;
    int n0 = blockIdx.y * BN;

    const float* A;
    const float* BT;
    float* C;
    if (MODE == MG1)      { A = nullptr; BT = g_W3T; C = g_H; }
    else if (MODE == MG2) { A = g_H;     BT = g_W4T; C = g_feat; }
    else if (MODE == MC1) { A = Aex;     BT = g_W1T; C = g_T1; }
    else if (MODE == MC2) { A = g_T1;    BT = g_W2T; C = g_Z; }
    else                  { A = g_Z;     BT = g_W5T; C = Cex; }

    int tid = threadIdx.x, wid = tid >> 5, lid = tid & 31;
    int gid = lid >> 2, ti = lid & 3;
    int warpM = wid & 1, warpN = wid >> 1;

    if (tid < BN) {
        bias_s[tid] = bias[n0 + tid];
        if (MODE == MG1) s64_s[tid] = g_s64[n0 + tid];
    }
    if (MODE == MG1) {
        if (tid < BM) {
            int rr = m0 + tid;
            if (rr < M) { pm_s[tid] = g_pm[rr]; w_s[tid] = g_w[rr]; }
            else { pm_s[tid] = make_float4(0.f,0.f,0.f,0.f); w_s[tid] = 0.f; }
        }
        if (tid >= 128 && tid < 192)
            coef_s[tid-128] = 6.2831853071795865f *
                              exp2f(-(float)(tid-128) * (13.287712379549450f/64.f));
    }
    __syncthreads();

    uint32_t* Asu = (uint32_t*)As;
    uint32_t* Bsu = (uint32_t*)Bs;
    uint32_t pa[8], pb[8];

    int a_row = tid >> 2, a_kq = (tid & 3) * 4;        // f = tid and tid+256 -> rows tid>>2, 64+tid>>2
    // loadA: fills pa[0..7] (two float4 groups: rows a_row and a_row+64)
    auto loadA = [&](int c) {
        #pragma unroll
        for (int i = 0; i < 2; i++) {
            int row = a_row + i*64;
            if (MODE == MG1) {
                float4 pm = pm_s[row]; float wv = w_s[row];
                const float* pmp = (const float*)&pm;
                #pragma unroll
                for (int u = 0; u < 4; u++) {
                    int j = c*BK + a_kq + u;
                    int a = j >> 8, sf = (j >> 7) & 1;
                    float ang = coef_s[(j & 127) >> 1] * pmp[2*a + sf];
                    float t = sf ? __cosf(ang) : __sinf(ang);
                    pa[i*4+u] = f2tf(t * wv);
                }
            } else {
                int gr = m0 + row;
                float4 v = make_float4(0.f,0.f,0.f,0.f);
                if (gr < M) v = *(const float4*)(A + (size_t)gr*Kd + c*BK + a_kq);
                pa[i*4+0] = f2tf(v.x); pa[i*4+1] = f2tf(v.y);
                pa[i*4+2] = f2tf(v.z); pa[i*4+3] = f2tf(v.w);
            }
        }
    };
    auto loadB = [&](int c) {
        #pragma unroll
        for (int i = 0; i < 2; i++) {
            int n = a_row + i*64;
            float4 v = *(const float4*)(BT + (size_t)(n0 + n)*Kd + c*BK + a_kq);
            pb[i*4+0] = f2tf(v.x); pb[i*4+1] = f2tf(v.y);
            pb[i*4+2] = f2tf(v.z); pb[i*4+3] = f2tf(v.w);
        }
    };
    auto store = [&]() {
        #pragma unroll
        for (int i = 0; i < 2; i++) {
            int row = a_row + i*64;
            *(uint4*)&Asu[row*AST + a_kq] = make_uint4(pa[i*4], pa[i*4+1], pa[i*4+2], pa[i*4+3]);
            *(uint4*)&Bsu[row*AST + a_kq] = make_uint4(pb[i*4], pb[i*4+1], pb[i*4+2], pb[i*4+3]);
        }
    };

    float acc[4][4][4];
    #pragma unroll
    for (int m = 0; m < 4; m++)
        #pragma unroll
        for (int n = 0; n < 4; n++)
            #pragma unroll
            for (int q = 0; q < 4; q++) acc[m][n][q] = 0.f;

    loadA(0); loadB(0);
    store();
    __syncthreads();

    const int nc = Kd / BK;
    for (int c = 0; c < nc; c++) {
        bool pf = (c + 1 < nc);
        if (pf) { loadA(c+1); loadB(c+1); }
        #pragma unroll
        for (int kb = 0; kb < BK; kb += 8) {
            uint32_t af[4][4], bf[4][2];
            #pragma unroll
            for (int m = 0; m < 4; m++) {
                int r0 = (warpM*64 + m*16 + gid) * AST + kb + ti;
                int r1 = r0 + 8*AST;
                af[m][0] = Asu[r0];     af[m][1] = Asu[r1];
                af[m][2] = Asu[r0 + 4]; af[m][3] = Asu[r1 + 4];
            }
            #pragma unroll
            for (int n = 0; n < 4; n++) {
                int cbr = (warpN*32 + n*8 + gid) * AST + kb + ti;
                bf[n][0] = Bsu[cbr]; bf[n][1] = Bsu[cbr + 4];
            }
            #pragma unroll
            for (int m = 0; m < 4; m++)
                #pragma unroll
                for (int n = 0; n < 4; n++)
                    mma_tf32(acc[m][n], af[m], bf[n]);
        }
        __syncthreads();
        if (pf) { store(); __syncthreads(); }
    }

    // ---- epilogue ----
    #pragma unroll
    for (int m = 0; m < 4; m++) {
        int r0 = m0 + warpM*64 + m*16 + gid;
        int r1 = r0 + 8;
        bool ok0 = r0 < M, ok1 = r1 < M;
        float ovl0 = 0.f, ovl1 = 0.f, ng0 = 1.f, ng1 = 1.f;
        if (MODE == MG1) {
            if (ok0) ovl0 = g_oval[r0];
            if (ok1) ovl1 = g_oval[r1];
        }
        if (MODE == MC2 || MODE == MOUT) {
            if (ok0) ng0 = 1.f - gmask[r0];
            if (ok1) ng1 = 1.f - gmask[r1];
        }
        #pragma unroll
        for (int n = 0; n < 4; n++) {
            int lc = warpN*32 + n*8 + ti*2;
            int col = n0 + lc;
            float b0 = bias_s[lc], b1 = bias_s[lc+1];
            #pragma unroll
            for (int h = 0; h < 2; h++) {
                int row = h ? r1 : r0;
                bool ok = h ? ok1 : ok0;
                if (!ok) continue;
                float ovl = h ? ovl1 : ovl0;
                float ng  = h ? ng1  : ng0;
                float v0 = acc[m][n][h*2+0] + b0;
                float v1 = acc[m][n][h*2+1] + b1;
                if (MODE == MG1) {
                    v0 = fmaxf(v0 + ovl * s64_s[lc],   0.f);
                    v1 = fmaxf(v1 + ovl * s64_s[lc+1], 0.f);
                } else if (MODE == MC1) {
                    v0 = fmaxf(v0, 0.f); v1 = fmaxf(v1, 0.f);
                } else if (MODE == MC2) {
                    const float* ar = g_agg + (size_t)row*DD + col;
                    v0 = v0 * ng + ar[0];
                    v1 = v1 * ng + ar[1];
                } else if (MODE == MOUT) {
                    v0 = fmaxf(v0, 0.f) * ng; v1 = fmaxf(v1, 0.f) * ng;
                }
                float2 o = make_float2(v0, v1);
                *(float2*)(C + (size_t)row*DD + col) = o;
            }
        }
    }
}

// ---------------- masked max over K neighbors -------------------------------
__global__ void k_reduce() {
    int r = blockIdx.x, d = threadIdx.x;
    int base = g_rowbase[r], cnt = g_rowcnt[r];
    float m = (cnt < KK) ? 0.0f : -3.4e38f;
    for (int e = 0; e < cnt; e++)
        m = fmaxf(m, g_mkval[base+e] * g_feat[(size_t)(base+e)*DD + d]);
    g_agg[(size_t)r*DD + d] = m;
}

// ---------------- launch ----------------------------------------------------
extern "C" void kernel_launch(void* const* d_in, const int* in_sizes, int n_in,
                              void* d_out, int out_size) {
    const float* tgt    = (const float*)d_in[0];
    const float* ious   = (const float*)d_in[1];
    const float* bboxes = (const float*)d_in[2];
    const float* gmask  = (const float*)d_in[3];
    const float* W1 = (const float*)d_in[4];  const float* b1 = (const float*)d_in[5];
    const float* W2 = (const float*)d_in[6];  const float* b2 = (const float*)d_in[7];
    const float* W3 = (const float*)d_in[8];  const float* b3 = (const float*)d_in[9];
    const float* W4 = (const float*)d_in[10]; const float* b4 = (const float*)d_in[11];
    const float* W5 = (const float*)d_in[12]; const float* b5 = (const float*)d_in[13];
    float* out = (float*)d_out;

    k_prep<<<1536, 256>>>(W1, W2, W3, W4, W5);
    k_init<<<1, 256>>>(W3);
    k_topk<<<(ROWS + 7) / 8, 256>>>(ious, gmask, bboxes);

    dim3 gdyn((FMAX + 127) / 128, 2);   // 563 x 2
    dim3 gfix((ROWS + 127) / 128, 2);   // 57 x 2

    gemm_mma<MG1><<<gdyn, 256>>>(nullptr, b3, nullptr, nullptr, 0);
    gemm_mma<MG2><<<gdyn, 256>>>(nullptr, b4, nullptr, nullptr, 0);
    k_reduce<<<ROWS, DD>>>();
    gemm_mma<MC1><<<gfix, 256>>>(tgt,     b1, nullptr, nullptr, ROWS);
    gemm_mma<MC2><<<gfix, 256>>>(nullptr, b2, gmask,  nullptr, ROWS);
    gemm_mma<MOUT><<<gfix, 256>>>(nullptr, b5, gmask, out,     ROWS);
}

// round 5
// speedup vs baseline: 2.6178x; 1.1614x over previous
#include <cuda_runtime.h>
#include <math.h>
#include <stdint.h>

#define BSZ 8
#define NQ 900
#define DD 256
#define KK 10
#define ROWS (BSZ*NQ)        /* 7200  */
#define FMAX (ROWS*KK)       /* 72000 */
#define WDIM 512

// ---------------- scratch (static __device__ arrays; no allocation) ----------
__device__ float4 g_pm[FMAX];
__device__ float  g_w[FMAX];
__device__ float  g_oval[FMAX];
__device__ float  g_mkval[FMAX];
__device__ float  g_H[(size_t)FMAX*DD];
__device__ float  g_feat[(size_t)FMAX*DD];
__device__ int    g_rowbase[ROWS];
__device__ int    g_rowcnt[ROWS];
__device__ float  g_T1[(size_t)ROWS*DD];
__device__ float  g_Z[(size_t)ROWS*DD];
__device__ float  g_agg[(size_t)ROWS*DD];
__device__ float  g_s64[DD];
__device__ int    g_count;
// transposed weights, [N][K] K-major rows
__device__ float  g_W3T[DD*WDIM];
__device__ float  g_W1T[DD*DD];
__device__ float  g_W2T[DD*DD];
__device__ float  g_W4T[DD*DD];
__device__ float  g_W5T[DD*DD];

__device__ __forceinline__ uint32_t f2tf(float f) {
    uint32_t r;
    asm("cvt.rna.tf32.f32 %0, %1;" : "=r"(r) : "f"(f));
    return r;
}
__device__ __forceinline__ void mma_tf32(float* c, const uint32_t* a, const uint32_t* b) {
    asm volatile(
        "mma.sync.aligned.m16n8k8.row.col.f32.tf32.tf32.f32 "
        "{%0,%1,%2,%3}, {%4,%5,%6,%7}, {%8,%9}, {%0,%1,%2,%3};"
        : "+f"(c[0]), "+f"(c[1]), "+f"(c[2]), "+f"(c[3])
        : "r"(a[0]), "r"(a[1]), "r"(a[2]), "r"(a[3]), "r"(b[0]), "r"(b[1]));
}
__device__ __forceinline__ void ldsm4(uint32_t* r, uint32_t addr) {
    asm volatile("ldmatrix.sync.aligned.m8n8.x4.shared.b16 {%0,%1,%2,%3}, [%4];"
        : "=r"(r[0]), "=r"(r[1]), "=r"(r[2]), "=r"(r[3]) : "r"(addr));
}
__device__ __forceinline__ uint32_t smem_u32(const void* p) {
    uint32_t a;
    asm("{ .reg .u64 t; cvta.to.shared.u64 t, %1; cvt.u32.u64 %0, t; }" : "=r"(a) : "l"(p));
    return a;
}

// ---------------- prep: transpose weights + s64 + counter -------------------
__global__ void k_prep(const float* __restrict__ W1, const float* __restrict__ W2,
                       const float* __restrict__ W3, const float* __restrict__ W4,
                       const float* __restrict__ W5) {
    int idx = blockIdx.x * 256 + threadIdx.x;
    if (idx < 131072) {                       // W3T [256][512] from W3[64+k][n]
        int n = idx >> 9, k = idx & 511;
        g_W3T[idx] = W3[(size_t)(64 + k) * DD + n];
    } else {
        int r = idx - 131072;
        int m = r >> 16, e = r & 65535;
        int n = e >> 8, k = e & 255;
        if      (m == 0) g_W1T[e] = W1[(size_t)k*DD + n];
        else if (m == 1) g_W2T[e] = W2[(size_t)k*DD + n];
        else if (m == 2) g_W4T[e] = W4[(size_t)k*DD + n];
        else             g_W5T[e] = W5[(size_t)k*DD + n];
    }
}
__global__ void k_init(const float* __restrict__ W3) {
    int n = threadIdx.x;
    float s = 0.f;
    #pragma unroll 8
    for (int r = 0; r < 64; r++) s += W3[r*DD + n];
    g_s64[n] = s;
    if (n == 0) g_count = 0;
}

// ---------------- top-K: one warp per row, register-resident ----------------
#define NU 29   /* ceil(900/32) */
__global__ __launch_bounds__(256)
void k_topk(const float* __restrict__ ious,
            const float* __restrict__ gmask,
            const float* __restrict__ bboxes) {
    int wid = threadIdx.x >> 5, lid = threadIdx.x & 31;
    int r = blockIdx.x * 8 + wid;
    if (r >= ROWS) return;
    int b = r / NQ, i = r % NQ;
    const float* Mrow = gmask + b*NQ;
    float neg_i = 1.0f - Mrow[i];
    if (neg_i == 0.0f) {
        if (lid == 0) { g_rowbase[r] = 0; g_rowcnt[r] = 0; }
        return;
    }
    const float* irow = ious + (size_t)r * NQ;
    float ov[NU];
    #pragma unroll
    for (int u = 0; u < NU; u++) {
        int j = lid + u*32;
        ov[u] = (j < NQ) ? irow[j] * Mrow[j] * neg_i : -3.4e38f;
    }
    float kv[KK]; int ki[KK];
    float lastv = 3.5e38f; int lasti = -1;
    #pragma unroll
    for (int t = 0; t < KK; t++) {
        float lv = -3.4e38f; int li = NQ;
        #pragma unroll
        for (int u = 0; u < NU; u++) {
            int j = lid + u*32;
            float v = ov[u];
            bool inc = (v < lastv) || (v == lastv && j > lasti);
            if (inc && (v > lv || (v == lv && j < li))) { lv = v; li = j; }
        }
        #pragma unroll
        for (int off = 16; off > 0; off >>= 1) {
            float vv = __shfl_xor_sync(0xffffffffu, lv, off);
            int   ii = __shfl_xor_sync(0xffffffffu, li, off);
            if (vv > lv || (vv == lv && ii < li)) { lv = vv; li = ii; }
        }
        kv[t] = lv; ki[t] = li;
        lastv = lv; lasti = li;
    }
    if (lid == 0) {
        float mkv[KK];
        int cnt = 0;
        #pragma unroll
        for (int t = 0; t < KK; t++) {
            float nmk = Mrow[ki[t]];
            float mk  = (kv[t] >= 0.4f) ? nmk : 0.0f;
            mkv[t] = mk;
            if (mk != 0.0f) cnt++;
        }
        int base = (cnt > 0) ? atomicAdd(&g_count, cnt) : 0;
        g_rowbase[r] = base; g_rowcnt[r] = cnt;

        const float* cb = bboxes + (size_t)r * 4;
        float ccx = 0.5f*(cb[0]+cb[2]), ccy = 0.5f*(cb[1]+cb[3]);
        float cw = cb[2]-cb[0], ch = cb[3]-cb[1];
        int s = 0;
        #pragma unroll
        for (int t = 0; t < KK; t++) {
            if (mkv[t] == 0.0f) continue;
            const float* nb = bboxes + (size_t)(b*NQ + ki[t]) * 4;
            float dcx = 0.5f*(nb[0]+nb[2]) - ccx;
            float dcy = 0.5f*(nb[1]+nb[3]) - ccy;
            float dw  = (nb[2]-nb[0]) - cw;
            float dh  = (nb[3]-nb[1]) - ch;
            float4 pm;
            pm.x = logf(fmaxf(fabsf(dcx), 1e-7f));
            pm.y = logf(fmaxf(fabsf(dcy), 1e-7f));
            pm.z = logf(fmaxf(fabsf(dw ), 1e-7f));
            pm.w = logf(fmaxf(fabsf(dh ), 1e-7f));
            g_pm[base+s]    = pm;
            g_w[base+s]     = neg_i * Mrow[ki[t]] * mkv[t];
            g_oval[base+s]  = kv[t] * mkv[t];
            g_mkval[base+s] = mkv[t];
            s++;
        }
    }
}

// ---------------- tf32 mma.sync GEMM: 128x128 tile, BK=16, ldmatrix ---------
enum { MG1 = 0, MG2 = 1, MC1 = 2, MC2 = 3, MOUT = 4 };
#define BM 128
#define BN 128
#define BK 16
#define AST 20   /* padded row stride (floats); 80B -> conflict-free ldmatrix */

template<int MODE>
__global__ __launch_bounds__(256)
void gemm_mma(const float* __restrict__ Aex,
              const float* __restrict__ bias,
              const float* __restrict__ gmask,
              float* __restrict__ Cex,
              int Mext) {
    __shared__ __align__(16) float As[BM*AST];
    __shared__ __align__(16) float Bs[BN*AST];
    __shared__ float bias_s[BN];
    __shared__ float s64_s[BN];
    __shared__ float4 pm_s[BM];
    __shared__ float w_s[BM];
    __shared__ float coef_s[64];

    const int Kd = (MODE == MG1) ? WDIM : DD;
    int M = (MODE == MG1 || MODE == MG2) ? g_count : Mext;
    int m0 = blockIdx.x * BM;
    if (m0 >= M) return;
    int n0 = blockIdx.y * BN;

    const float* A;
    const float* BT;
    float* C;
    if (MODE == MG1)      { A = nullptr; BT = g_W3T; C = g_H; }
    else if (MODE == MG2) { A = g_H;     BT = g_W4T; C = g_feat; }
    else if (MODE == MC1) { A = Aex;     BT = g_W1T; C = g_T1; }
    else if (MODE == MC2) { A = g_T1;    BT = g_W2T; C = g_Z; }
    else                  { A = g_Z;     BT = g_W5T; C = Cex; }

    int tid = threadIdx.x, wid = tid >> 5, lid = tid & 31;
    int gid = lid >> 2, ti = lid & 3;
    int warpM = wid & 1, warpN = wid >> 1;

    if (tid < BN) {
        bias_s[tid] = bias[n0 + tid];
        if (MODE == MG1) s64_s[tid] = g_s64[n0 + tid];
    }
    if (MODE == MG1) {
        if (tid < BM) {
            int rr = m0 + tid;
            if (rr < M) { pm_s[tid] = g_pm[rr]; w_s[tid] = g_w[rr]; }
            else { pm_s[tid] = make_float4(0.f,0.f,0.f,0.f); w_s[tid] = 0.f; }
        }
        if (tid >= 128 && tid < 192)
            coef_s[tid-128] = 6.2831853071795865f *
                              exp2f(-(float)(tid-128) * (13.287712379549450f/64.f));
    }
    __syncthreads();

    uint32_t* Asu = (uint32_t*)As;
    uint32_t* Bsu = (uint32_t*)Bs;
    uint32_t pa[8], pb[8];

    int a_row = tid >> 2, a_kq = (tid & 3) * 4;
    auto loadA = [&](int c) {
        #pragma unroll
        for (int i = 0; i < 2; i++) {
            int row = a_row + i*64;
            if (MODE == MG1) {
                float4 pm = pm_s[row]; float wv = w_s[row];
                const float* pmp = (const float*)&pm;
                #pragma unroll
                for (int u = 0; u < 4; u++) {
                    int j = c*BK + a_kq + u;
                    int a = j >> 8, sf = (j >> 7) & 1;
                    float ang = coef_s[(j & 127) >> 1] * pmp[2*a + sf];
                    float t = sf ? __cosf(ang) : __sinf(ang);
                    pa[i*4+u] = f2tf(t * wv);
                }
            } else {
                int gr = m0 + row;
                float4 v = make_float4(0.f,0.f,0.f,0.f);
                if (gr < M) v = *(const float4*)(A + (size_t)gr*Kd + c*BK + a_kq);
                pa[i*4+0] = f2tf(v.x); pa[i*4+1] = f2tf(v.y);
                pa[i*4+2] = f2tf(v.z); pa[i*4+3] = f2tf(v.w);
            }
        }
    };
    auto loadB = [&](int c) {
        #pragma unroll
        for (int i = 0; i < 2; i++) {
            int n = a_row + i*64;
            float4 v = *(const float4*)(BT + (size_t)(n0 + n)*Kd + c*BK + a_kq);
            pb[i*4+0] = f2tf(v.x); pb[i*4+1] = f2tf(v.y);
            pb[i*4+2] = f2tf(v.z); pb[i*4+3] = f2tf(v.w);
        }
    };
    auto store = [&]() {
        #pragma unroll
        for (int i = 0; i < 2; i++) {
            int row = a_row + i*64;
            *(uint4*)&Asu[row*AST + a_kq] = make_uint4(pa[i*4], pa[i*4+1], pa[i*4+2], pa[i*4+3]);
            *(uint4*)&Bsu[row*AST + a_kq] = make_uint4(pb[i*4], pb[i*4+1], pb[i*4+2], pb[i*4+3]);
        }
    };

    // ---- ldmatrix per-lane addresses (bytes) ----
    // A x4 subtiles for one m-block: (r..r+7,k0-3)(r+8..r+15,k0-3)(r..r+7,k4-7)(r+8..,k4-7)
    uint32_t As_b = smem_u32(As);
    uint32_t Bs_b = smem_u32(Bs);
    int arow_l = (lid & 7) + ((lid >> 3) & 1) * 8;
    int akq_l  = (lid >> 4) * 4;
    uint32_t aaddr = As_b + (uint32_t)(((warpM*64 + arow_l) * AST + akq_l) * 4);
    int brow_l = (lid & 7) + (lid >> 4) * 8;
    int bkq_l  = ((lid >> 3) & 1) * 4;
    uint32_t baddr = Bs_b + (uint32_t)(((warpN*32 + brow_l) * AST + bkq_l) * 4);

    float acc[4][4][4];
    #pragma unroll
    for (int m = 0; m < 4; m++)
        #pragma unroll
        for (int n = 0; n < 4; n++)
            #pragma unroll
            for (int q = 0; q < 4; q++) acc[m][n][q] = 0.f;

    loadA(0); loadB(0);
    store();
    __syncthreads();

    const int nc = Kd / BK;
    for (int c = 0; c < nc; c++) {
        bool pf = (c + 1 < nc);
        if (pf) { loadA(c+1); loadB(c+1); }
        #pragma unroll
        for (int kb = 0; kb < BK; kb += 8) {
            uint32_t af[4][4], bq[2][4];
            #pragma unroll
            for (int m = 0; m < 4; m++)
                ldsm4(af[m], aaddr + (uint32_t)((m*16*AST + kb) * 4));
            #pragma unroll
            for (int g = 0; g < 2; g++)
                ldsm4(bq[g], baddr + (uint32_t)((g*16*AST + kb) * 4));
            // bq[g] = { bf[2g][0], bf[2g][1], bf[2g+1][0], bf[2g+1][1] }
            #pragma unroll
            for (int m = 0; m < 4; m++) {
                #pragma unroll
                for (int n = 0; n < 4; n++) {
                    uint32_t bfr[2] = { bq[n>>1][(n&1)*2], bq[n>>1][(n&1)*2+1] };
                    mma_tf32(acc[m][n], af[m], bfr);
                }
            }
        }
        __syncthreads();
        if (pf) { store(); __syncthreads(); }
    }

    // ---- epilogue ----
    #pragma unroll
    for (int m = 0; m < 4; m++) {
        int r0 = m0 + warpM*64 + m*16 + gid;
        int r1 = r0 + 8;
        bool ok0 = r0 < M, ok1 = r1 < M;
        float ovl0 = 0.f, ovl1 = 0.f, ng0 = 1.f, ng1 = 1.f;
        if (MODE == MG1) {
            if (ok0) ovl0 = g_oval[r0];
            if (ok1) ovl1 = g_oval[r1];
        }
        if (MODE == MC2 || MODE == MOUT) {
            if (ok0) ng0 = 1.f - gmask[r0];
            if (ok1) ng1 = 1.f - gmask[r1];
        }
        #pragma unroll
        for (int n = 0; n < 4; n++) {
            int lc = warpN*32 + n*8 + ti*2;
            int col = n0 + lc;
            float b0 = bias_s[lc], b1 = bias_s[lc+1];
            #pragma unroll
            for (int h = 0; h < 2; h++) {
                int row = h ? r1 : r0;
                bool ok = h ? ok1 : ok0;
                if (!ok) continue;
                float ovl = h ? ovl1 : ovl0;
                float ng  = h ? ng1  : ng0;
                float v0 = acc[m][n][h*2+0] + b0;
                float v1 = acc[m][n][h*2+1] + b1;
                if (MODE == MG1) {
                    v0 = fmaxf(v0 + ovl * s64_s[lc],   0.f);
                    v1 = fmaxf(v1 + ovl * s64_s[lc+1], 0.f);
                } else if (MODE == MC1) {
                    v0 = fmaxf(v0, 0.f); v1 = fmaxf(v1, 0.f);
                } else if (MODE == MC2) {
                    const float* ar = g_agg + (size_t)row*DD + col;
                    v0 = v0 * ng + ar[0];
                    v1 = v1 * ng + ar[1];
                } else if (MODE == MOUT) {
                    v0 = fmaxf(v0, 0.f) * ng; v1 = fmaxf(v1, 0.f) * ng;
                }
                float2 o = make_float2(v0, v1);
                *(float2*)(C + (size_t)row*DD + col) = o;
            }
        }
    }
}

// ---------------- masked max over K neighbors -------------------------------
__global__ void k_reduce() {
    int r = blockIdx.x, d = threadIdx.x;
    int base = g_rowbase[r], cnt = g_rowcnt[r];
    float m = (cnt < KK) ? 0.0f : -3.4e38f;
    for (int e = 0; e < cnt; e++)
        m = fmaxf(m, g_mkval[base+e] * g_feat[(size_t)(base+e)*DD + d]);
    g_agg[(size_t)r*DD + d] = m;
}

// ---------------- launch ----------------------------------------------------
extern "C" void kernel_launch(void* const* d_in, const int* in_sizes, int n_in,
                              void* d_out, int out_size) {
    const float* tgt    = (const float*)d_in[0];
    const float* ious   = (const float*)d_in[1];
    const float* bboxes = (const float*)d_in[2];
    const float* gmask  = (const float*)d_in[3];
    const float* W1 = (const float*)d_in[4];  const float* b1 = (const float*)d_in[5];
    const float* W2 = (const float*)d_in[6];  const float* b2 = (const float*)d_in[7];
    const float* W3 = (const float*)d_in[8];  const float* b3 = (const float*)d_in[9];
    const float* W4 = (const float*)d_in[10]; const float* b4 = (const float*)d_in[11];
    const float* W5 = (const float*)d_in[12]; const float* b5 = (const float*)d_in[13];
    float* out = (float*)d_out;

    k_prep<<<1536, 256>>>(W1, W2, W3, W4, W5);
    k_init<<<1, 256>>>(W3);
    k_topk<<<(ROWS + 7) / 8, 256>>>(ious, gmask, bboxes);

    dim3 gdyn((FMAX + 127) / 128, 2);   // 563 x 2
    dim3 gfix((ROWS + 127) / 128, 2);   // 57 x 2

    gemm_mma<MG1><<<gdyn, 256>>>(nullptr, b3, nullptr, nullptr, 0);
    gemm_mma<MG2><<<gdyn, 256>>>(nullptr, b4, nullptr, nullptr, 0);
    k_reduce<<<ROWS, DD>>>();
    gemm_mma<MC1><<<gfix, 256>>>(tgt,     b1, nullptr, nullptr, ROWS);
    gemm_mma<MC2><<<gfix, 256>>>(nullptr, b2, gmask,  nullptr, ROWS);
    gemm_mma<MOUT><<<gfix, 256>>>(nullptr, b5, gmask, out,     ROWS);
}

// round 6
// speedup vs baseline: 3.0385x; 1.1607x over previous
#include <cuda_runtime.h>
#include <cuda_fp16.h>
#include <math.h>
#include <stdint.h>

#define BSZ 8
#define NQ 900
#define DD 256
#define KK 10
#define ROWS (BSZ*NQ)        /* 7200  */
#define FMAX (ROWS*KK)       /* 72000 */
#define WDIM 512

// ---------------- scratch (static __device__ arrays; no allocation) ----------
__device__ float4 g_pm[FMAX];
__device__ float  g_w[FMAX];
__device__ float  g_oval[FMAX];
__device__ float  g_mkval[FMAX];
__device__ float  g_H[(size_t)FMAX*DD];
__device__ float  g_feat[(size_t)FMAX*DD];
__device__ int    g_rowbase[ROWS];
__device__ int    g_rowcnt[ROWS];
__device__ float  g_T1[(size_t)ROWS*DD];
__device__ float  g_Z[(size_t)ROWS*DD];
__device__ float  g_agg[(size_t)ROWS*DD];
__device__ float  g_s64[DD];
__device__ int    g_count;
// transposed weights, [N][K] K-major rows, fp16
__device__ __half g_W3T[DD*WDIM];
__device__ __half g_W1T[DD*DD];
__device__ __half g_W2T[DD*DD];
__device__ __half g_W4T[DD*DD];
__device__ __half g_W5T[DD*DD];

__device__ __forceinline__ void mma_f16(float* c, const uint32_t* a, const uint32_t* b) {
    asm volatile(
        "mma.sync.aligned.m16n8k16.row.col.f32.f16.f16.f32 "
        "{%0,%1,%2,%3}, {%4,%5,%6,%7}, {%8,%9}, {%0,%1,%2,%3};"
        : "+f"(c[0]), "+f"(c[1]), "+f"(c[2]), "+f"(c[3])
        : "r"(a[0]), "r"(a[1]), "r"(a[2]), "r"(a[3]), "r"(b[0]), "r"(b[1]));
}
__device__ __forceinline__ void ldsm4(uint32_t* r, uint32_t addr) {
    asm volatile("ldmatrix.sync.aligned.m8n8.x4.shared.b16 {%0,%1,%2,%3}, [%4];"
        : "=r"(r[0]), "=r"(r[1]), "=r"(r[2]), "=r"(r[3]) : "r"(addr));
}
__device__ __forceinline__ uint32_t smem_u32(const void* p) {
    uint32_t a;
    asm("{ .reg .u64 t; cvta.to.shared.u64 t, %1; cvt.u32.u64 %0, t; }" : "=r"(a) : "l"(p));
    return a;
}
__device__ __forceinline__ uint32_t packh2(float a, float b) {
    __half2 h = __floats2half2_rn(a, b);
    return *(uint32_t*)&h;
}

// ---------------- prep: transpose weights (to fp16) + s64 + counter ---------
__global__ void k_prep(const float* __restrict__ W1, const float* __restrict__ W2,
                       const float* __restrict__ W3, const float* __restrict__ W4,
                       const float* __restrict__ W5) {
    int idx = blockIdx.x * 256 + threadIdx.x;
    if (idx < 131072) {                       // W3T [256][512] from W3[64+k][n]
        int n = idx >> 9, k = idx & 511;
        g_W3T[idx] = __float2half(W3[(size_t)(64 + k) * DD + n]);
    } else {
        int r = idx - 131072;
        int m = r >> 16, e = r & 65535;
        int n = e >> 8, k = e & 255;
        if      (m == 0) g_W1T[e] = __float2half(W1[(size_t)k*DD + n]);
        else if (m == 1) g_W2T[e] = __float2half(W2[(size_t)k*DD + n]);
        else if (m == 2) g_W4T[e] = __float2half(W4[(size_t)k*DD + n]);
        else             g_W5T[e] = __float2half(W5[(size_t)k*DD + n]);
    }
}
__global__ void k_init(const float* __restrict__ W3) {
    int n = threadIdx.x;
    float s = 0.f;
    #pragma unroll 8
    for (int r = 0; r < 64; r++) s += W3[r*DD + n];
    g_s64[n] = s;
    if (n == 0) g_count = 0;
}

// ---------------- top-K: one warp per row, register-resident ----------------
#define NU 29   /* ceil(900/32) */
__global__ __launch_bounds__(256)
void k_topk(const float* __restrict__ ious,
            const float* __restrict__ gmask,
            const float* __restrict__ bboxes) {
    int wid = threadIdx.x >> 5, lid = threadIdx.x & 31;
    int r = blockIdx.x * 8 + wid;
    if (r >= ROWS) return;
    int b = r / NQ, i = r % NQ;
    const float* Mrow = gmask + b*NQ;
    float neg_i = 1.0f - Mrow[i];
    if (neg_i == 0.0f) {
        if (lid == 0) { g_rowbase[r] = 0; g_rowcnt[r] = 0; }
        return;
    }
    const float* irow = ious + (size_t)r * NQ;
    float ov[NU];
    #pragma unroll
    for (int u = 0; u < NU; u++) {
        int j = lid + u*32;
        ov[u] = (j < NQ) ? irow[j] * Mrow[j] * neg_i : -3.4e38f;
    }
    float kv[KK]; int ki[KK];
    float lastv = 3.5e38f; int lasti = -1;
    #pragma unroll
    for (int t = 0; t < KK; t++) {
        float lv = -3.4e38f; int li = NQ;
        #pragma unroll
        for (int u = 0; u < NU; u++) {
            int j = lid + u*32;
            float v = ov[u];
            bool inc = (v < lastv) || (v == lastv && j > lasti);
            if (inc && (v > lv || (v == lv && j < li))) { lv = v; li = j; }
        }
        #pragma unroll
        for (int off = 16; off > 0; off >>= 1) {
            float vv = __shfl_xor_sync(0xffffffffu, lv, off);
            int   ii = __shfl_xor_sync(0xffffffffu, li, off);
            if (vv > lv || (vv == lv && ii < li)) { lv = vv; li = ii; }
        }
        kv[t] = lv; ki[t] = li;
        lastv = lv; lasti = li;
    }
    if (lid == 0) {
        float mkv[KK];
        int cnt = 0;
        #pragma unroll
        for (int t = 0; t < KK; t++) {
            float nmk = Mrow[ki[t]];
            float mk  = (kv[t] >= 0.4f) ? nmk : 0.0f;
            mkv[t] = mk;
            if (mk != 0.0f) cnt++;
        }
        int base = (cnt > 0) ? atomicAdd(&g_count, cnt) : 0;
        g_rowbase[r] = base; g_rowcnt[r] = cnt;

        const float* cb = bboxes + (size_t)r * 4;
        float ccx = 0.5f*(cb[0]+cb[2]), ccy = 0.5f*(cb[1]+cb[3]);
        float cw = cb[2]-cb[0], ch = cb[3]-cb[1];
        int s = 0;
        #pragma unroll
        for (int t = 0; t < KK; t++) {
            if (mkv[t] == 0.0f) continue;
            const float* nb = bboxes + (size_t)(b*NQ + ki[t]) * 4;
            float dcx = 0.5f*(nb[0]+nb[2]) - ccx;
            float dcy = 0.5f*(nb[1]+nb[3]) - ccy;
            float dw  = (nb[2]-nb[0]) - cw;
            float dh  = (nb[3]-nb[1]) - ch;
            float4 pm;
            pm.x = logf(fmaxf(fabsf(dcx), 1e-7f));
            pm.y = logf(fmaxf(fabsf(dcy), 1e-7f));
            pm.z = logf(fmaxf(fabsf(dw ), 1e-7f));
            pm.w = logf(fmaxf(fabsf(dh ), 1e-7f));
            g_pm[base+s]    = pm;
            g_w[base+s]     = neg_i * Mrow[ki[t]] * mkv[t];
            g_oval[base+s]  = kv[t] * mkv[t];
            g_mkval[base+s] = mkv[t];
            s++;
        }
    }
}

// ---------------- fp16 mma.sync GEMM: 128x128 tile, BK=32, ldmatrix ---------
enum { MG1 = 0, MG2 = 1, MC1 = 2, MC2 = 3, MOUT = 4 };
#define BM 128
#define BN 128
#define BK 32     /* fp16 k-elements per chunk */
#define PADH 40   /* padded row stride in fp16 units; 80B -> conflict-free ldmatrix */

template<int MODE>
__global__ __launch_bounds__(256)
void gemm_mma(const float* __restrict__ Aex,
              const float* __restrict__ bias,
              const float* __restrict__ gmask,
              float* __restrict__ Cex,
              int Mext) {
    __shared__ __align__(16) __half Ash[BM*PADH];
    __shared__ __align__(16) __half Bsh[BN*PADH];
    __shared__ float bias_s[BN];
    __shared__ float s64_s[BN];
    __shared__ float4 pm_s[BM];
    __shared__ float w_s[BM];
    __shared__ float coef_s[64];

    const int Kd = (MODE == MG1) ? WDIM : DD;
    int M = (MODE == MG1 || MODE == MG2) ? g_count : Mext;
    int m0 = blockIdx.x * BM;
    if (m0 >= M) return;
    int n0 = blockIdx.y * BN;

    const float* A;
    const __half* BT;
    float* C;
    if (MODE == MG1)      { A = nullptr; BT = g_W3T; C = g_H; }
    else if (MODE == MG2) { A = g_H;     BT = g_W4T; C = g_feat; }
    else if (MODE == MC1) { A = Aex;     BT = g_W1T; C = g_T1; }
    else if (MODE == MC2) { A = g_T1;    BT = g_W2T; C = g_Z; }
    else                  { A = g_Z;     BT = g_W5T; C = Cex; }

    int tid = threadIdx.x, wid = tid >> 5, lid = tid & 31;
    int gid = lid >> 2, ti = lid & 3;
    int warpM = wid & 1, warpN = wid >> 1;

    if (tid < BN) {
        bias_s[tid] = bias[n0 + tid];
        if (MODE == MG1) s64_s[tid] = g_s64[n0 + tid];
    }
    if (MODE == MG1) {
        if (tid < BM) {
            int rr = m0 + tid;
            if (rr < M) { pm_s[tid] = g_pm[rr]; w_s[tid] = g_w[rr]; }
            else { pm_s[tid] = make_float4(0.f,0.f,0.f,0.f); w_s[tid] = 0.f; }
        }
        if (tid >= 128 && tid < 192)
            coef_s[tid-128] = 6.2831853071795865f *
                              exp2f(-(float)(tid-128) * (13.287712379549450f/64.f));
    }
    __syncthreads();

    // staging: thread -> row tid>>1 (0..127), half-chunk kh=(tid&1)*16 fp16
    int s_row = tid >> 1;
    int s_kh  = (tid & 1) * 16;
    uint32_t pa[8], pb[8];

    auto loadA = [&](int c) {
        if (MODE == MG1) {
            float4 pm = pm_s[s_row]; float wv = w_s[s_row];
            const float* pmp = (const float*)&pm;
            float v[16];
            #pragma unroll
            for (int u = 0; u < 16; u++) {
                int j = c*BK + s_kh + u;
                int a = j >> 8, sf = (j >> 7) & 1;
                float ang = coef_s[(j & 127) >> 1] * pmp[2*a + sf];
                float t = sf ? __cosf(ang) : __sinf(ang);
                v[u] = t * wv;
            }
            #pragma unroll
            for (int u = 0; u < 8; u++) pa[u] = packh2(v[2*u], v[2*u+1]);
        } else {
            int gr = m0 + s_row;
            const float* ap = A + (size_t)gr*Kd + c*BK + s_kh;
            #pragma unroll
            for (int q = 0; q < 4; q++) {
                float4 fv = make_float4(0.f,0.f,0.f,0.f);
                if (gr < M) fv = *(const float4*)(ap + q*4);
                pa[q*2+0] = packh2(fv.x, fv.y);
                pa[q*2+1] = packh2(fv.z, fv.w);
            }
        }
    };
    auto loadB = [&](int c) {
        const uint4* bp = (const uint4*)(BT + (size_t)(n0 + s_row)*Kd + c*BK + s_kh);
        uint4 v0 = bp[0], v1 = bp[1];
        pb[0]=v0.x; pb[1]=v0.y; pb[2]=v0.z; pb[3]=v0.w;
        pb[4]=v1.x; pb[5]=v1.y; pb[6]=v1.z; pb[7]=v1.w;
    };
    auto store = [&]() {
        uint32_t* ad = (uint32_t*)&Ash[s_row*PADH + s_kh];
        uint32_t* bd = (uint32_t*)&Bsh[s_row*PADH + s_kh];
        *(uint4*)(ad)     = make_uint4(pa[0], pa[1], pa[2], pa[3]);
        *(uint4*)(ad + 4) = make_uint4(pa[4], pa[5], pa[6], pa[7]);
        *(uint4*)(bd)     = make_uint4(pb[0], pb[1], pb[2], pb[3]);
        *(uint4*)(bd + 4) = make_uint4(pb[4], pb[5], pb[6], pb[7]);
    };

    // ldmatrix per-lane addresses (bytes): row = lid&15, k-octet = (lid>>4)*8 fp16
    uint32_t As_b = smem_u32(Ash);
    uint32_t Bs_b = smem_u32(Bsh);
    int l16 = lid & 15, lk = (lid >> 4) * 8;
    uint32_t aaddr = As_b + (uint32_t)((warpM*64 + l16) * PADH + lk) * 2u;
    uint32_t baddr = Bs_b + (uint32_t)((warpN*32 + l16) * PADH + lk) * 2u;

    float acc[4][4][4];
    #pragma unroll
    for (int m = 0; m < 4; m++)
        #pragma unroll
        for (int n = 0; n < 4; n++)
            #pragma unroll
            for (int q = 0; q < 4; q++) acc[m][n][q] = 0.f;

    loadA(0); loadB(0);
    store();
    __syncthreads();

    const int nc = Kd / BK;
    for (int c = 0; c < nc; c++) {
        bool pf = (c + 1 < nc);
        if (pf) { loadA(c+1); loadB(c+1); }
        #pragma unroll
        for (int kb = 0; kb < BK; kb += 16) {
            uint32_t af[4][4], bq[2][4];
            #pragma unroll
            for (int m = 0; m < 4; m++)
                ldsm4(af[m], aaddr + (uint32_t)((m*16*PADH + kb) * 2));
            #pragma unroll
            for (int g = 0; g < 2; g++)
                ldsm4(bq[g], baddr + (uint32_t)((g*16*PADH + kb) * 2));
            // bq[g] subtiles: {n0-7 k0-7, n8-15 k0-7, n0-7 k8-15, n8-15 k8-15}
            #pragma unroll
            for (int m = 0; m < 4; m++) {
                #pragma unroll
                for (int n = 0; n < 4; n++) {
                    uint32_t bfr[2] = { bq[n>>1][n&1], bq[n>>1][(n&1)+2] };
                    mma_f16(acc[m][n], af[m], bfr);
                }
            }
        }
        __syncthreads();
        if (pf) { store(); __syncthreads(); }
    }

    // ---- epilogue (same C-fragment mapping as m16n8k8) ----
    #pragma unroll
    for (int m = 0; m < 4; m++) {
        int r0 = m0 + warpM*64 + m*16 + gid;
        int r1 = r0 + 8;
        bool ok0 = r0 < M, ok1 = r1 < M;
        float ovl0 = 0.f, ovl1 = 0.f, ng0 = 1.f, ng1 = 1.f;
        if (MODE == MG1) {
            if (ok0) ovl0 = g_oval[r0];
            if (ok1) ovl1 = g_oval[r1];
        }
        if (MODE == MC2 || MODE == MOUT) {
            if (ok0) ng0 = 1.f - gmask[r0];
            if (ok1) ng1 = 1.f - gmask[r1];
        }
        #pragma unroll
        for (int n = 0; n < 4; n++) {
            int lc = warpN*32 + n*8 + ti*2;
            int col = n0 + lc;
            float b0 = bias_s[lc], b1 = bias_s[lc+1];
            #pragma unroll
            for (int h = 0; h < 2; h++) {
                int row = h ? r1 : r0;
                bool ok = h ? ok1 : ok0;
                if (!ok) continue;
                float ovl = h ? ovl1 : ovl0;
                float ng  = h ? ng1  : ng0;
                float v0 = acc[m][n][h*2+0] + b0;
                float v1 = acc[m][n][h*2+1] + b1;
                if (MODE == MG1) {
                    v0 = fmaxf(v0 + ovl * s64_s[lc],   0.f);
                    v1 = fmaxf(v1 + ovl * s64_s[lc+1], 0.f);
                } else if (MODE == MC1) {
                    v0 = fmaxf(v0, 0.f); v1 = fmaxf(v1, 0.f);
                } else if (MODE == MC2) {
                    const float* ar = g_agg + (size_t)row*DD + col;
                    v0 = v0 * ng + ar[0];
                    v1 = v1 * ng + ar[1];
                } else if (MODE == MOUT) {
                    v0 = fmaxf(v0, 0.f) * ng; v1 = fmaxf(v1, 0.f) * ng;
                }
                float2 o = make_float2(v0, v1);
                *(float2*)(C + (size_t)row*DD + col) = o;
            }
        }
    }
}

// ---------------- masked max over K neighbors -------------------------------
__global__ void k_reduce() {
    int r = blockIdx.x, d = threadIdx.x;
    int base = g_rowbase[r], cnt = g_rowcnt[r];
    float m = (cnt < KK) ? 0.0f : -3.4e38f;
    for (int e = 0; e < cnt; e++)
        m = fmaxf(m, g_mkval[base+e] * g_feat[(size_t)(base+e)*DD + d]);
    g_agg[(size_t)r*DD + d] = m;
}

// ---------------- launch ----------------------------------------------------
extern "C" void kernel_launch(void* const* d_in, const int* in_sizes, int n_in,
                              void* d_out, int out_size) {
    const float* tgt    = (const float*)d_in[0];
    const float* ious   = (const float*)d_in[1];
    const float* bboxes = (const float*)d_in[2];
    const float* gmask  = (const float*)d_in[3];
    const float* W1 = (const float*)d_in[4];  const float* b1 = (const float*)d_in[5];
    const float* W2 = (const float*)d_in[6];  const float* b2 = (const float*)d_in[7];
    const float* W3 = (const float*)d_in[8];  const float* b3 = (const float*)d_in[9];
    const float* W4 = (const float*)d_in[10]; const float* b4 = (const float*)d_in[11];
    const float* W5 = (const float*)d_in[12]; const float* b5 = (const float*)d_in[13];
    float* out = (float*)d_out;

    k_prep<<<1536, 256>>>(W1, W2, W3, W4, W5);
    k_init<<<1, 256>>>(W3);
    k_topk<<<(ROWS + 7) / 8, 256>>>(ious, gmask, bboxes);

    dim3 gdyn((FMAX + 127) / 128, 2);   // 563 x 2
    dim3 gfix((ROWS + 127) / 128, 2);   // 57 x 2

    gemm_mma<MG1><<<gdyn, 256>>>(nullptr, b3, nullptr, nullptr, 0);
    gemm_mma<MG2><<<gdyn, 256>>>(nullptr, b4, nullptr, nullptr, 0);
    k_reduce<<<ROWS, DD>>>();
    gemm_mma<MC1><<<gfix, 256>>>(tgt,     b1, nullptr, nullptr, ROWS);
    gemm_mma<MC2><<<gfix, 256>>>(nullptr, b2, gmask,  nullptr, ROWS);
    gemm_mma<MOUT><<<gfix, 256>>>(nullptr, b5, gmask, out,     ROWS);
}